// round 10
// baseline (speedup 1.0000x reference)
#include <cuda_runtime.h>
#include <cuda_bf16.h>
#include <cstdint>
#include <cstddef>

#define D_DIM  2048
#define NEXP   64
#define TILE_M 128
#define KC     32
#define NCH    (D_DIM / KC)   // 64 chunks
#define NTHR   256
#define MARGIN 4e-4f
#define MAXC   16

// ---- smem layout (bytes) ----
// A: fp32, row stride 160B (128 data + 32 pad) -> LDS.64 frag pattern (8g+2tg) conflict-free
// B: bf16, row stride 80B (64 data + 16 pad)   -> LDS.32 frag pattern (20g+tg) conflict-free
#define A_OFF    0
#define A_STG    20480            // 128 * 160
#define BH_OFF   61440            // 3 * A_STG
#define B_STG    5120             // 64 * 80
#define BL_OFF   76800
#define BIAS_OFF 92160
#define SMEM_TOTAL 92416
#define LG_PAD   66

__device__ __nv_bfloat16 g_Wh[NEXP * D_DIM];   // RN bf16 hi of W
__device__ __nv_bfloat16 g_Wm[NEXP * D_DIM];   // RN bf16 of residual

// ---------------- helpers ----------------
__device__ __forceinline__ uint32_t smem_u32(const void* p) {
    uint32_t a;
    asm("{ .reg .u64 t; cvta.to.shared.u64 t, %1; cvt.u32.u64 %0, t; }" : "=r"(a) : "l"(p));
    return a;
}
__device__ __forceinline__ void cpa16(void* dst, const void* src) {
    asm volatile("cp.async.cg.shared.global [%0], [%1], 16;"
                 :: "r"(smem_u32(dst)), "l"(src) : "memory");
}
#define CP_COMMIT() asm volatile("cp.async.commit_group;" ::: "memory")
#define CP_WAIT(n)  asm volatile("cp.async.wait_group %0;" :: "n"(n) : "memory")

__device__ __forceinline__ void mma_bf16(float* c, const uint32_t* a, uint32_t b0, uint32_t b1) {
    asm volatile("mma.sync.aligned.m16n8k16.row.col.f32.bf16.bf16.f32 "
        "{%0,%1,%2,%3}, {%4,%5,%6,%7}, {%8,%9}, {%0,%1,%2,%3};"
        : "+f"(c[0]), "+f"(c[1]), "+f"(c[2]), "+f"(c[3])
        : "r"(a[0]), "r"(a[1]), "r"(a[2]), "r"(a[3]), "r"(b0), "r"(b1));
}

// register split of a float2 (k-adjacent pair) into hi-bf16x2 (truncation) + lo-bf16x2 (RN)
__device__ __forceinline__ void splitpair(float x, float y, uint32_t& hi, uint32_t& lo) {
    uint32_t xb = __float_as_uint(x), yb = __float_as_uint(y);
    hi = __byte_perm(xb, yb, 0x7632);                       // {lo=trunc16(x), hi=trunc16(y)}
    float lx = x - __uint_as_float(xb & 0xFFFF0000u);       // exact
    float ly = y - __uint_as_float(yb & 0xFFFF0000u);
    asm("cvt.rn.bf16x2.f32 %0, %1, %2;" : "=r"(lo) : "f"(ly), "f"(lx));
}

// ---------------- W pre-split (RN 2-way) ----------------
__global__ void conv_w_kernel(const float* __restrict__ W) {
    int i = blockIdx.x * 256 + threadIdx.x;
    float x = W[i];
    __nv_bfloat16 h = __float2bfloat16(x);
    __nv_bfloat16 m = __float2bfloat16(x - __bfloat162float(h));
    g_Wh[i] = h; g_Wm[i] = m;
}

// ---------------- main fused kernel ----------------
__global__ __launch_bounds__(NTHR, 2)
void moe_gate_mma(const float* __restrict__ r, const float* __restrict__ W,
                  const float* __restrict__ bias,
                  float* __restrict__ out, size_t soft_base)
{
    extern __shared__ char smem[];
    const int tid  = threadIdx.x;
    const int warp = tid >> 5, lane = tid & 31;
    const int g    = lane >> 2, tg = lane & 3;
    const int wm   = warp & 3, wn = warp >> 2;     // warp grid: 4 in M x 2 in N
    const int row0 = blockIdx.x * TILE_M;

    if (tid < NEXP) *(float*)(smem + BIAS_OFF + tid * 4) = bias[tid];

    auto issue = [&](int ci) {
        const int s  = ci % 3;
        const int k0 = ci * KC;
#pragma unroll
        for (int i = 0; i < 4; i++) {                 // A: 128 rows x 8 x 16B
            int id = tid + i * NTHR;
            int row = id >> 3, seg = id & 7;
            cpa16(smem + A_OFF + s * A_STG + row * 160 + seg * 16,
                  r + (size_t)(row0 + row) * D_DIM + k0 + seg * 4);
        }
        {                                             // B hi/lo: 64 rows x 4 x 16B each
            int e = tid >> 2, seg = tid & 3;
            cpa16(smem + BH_OFF + s * B_STG + e * 80 + seg * 16,
                  g_Wh + (size_t)e * D_DIM + k0 + seg * 8);
            cpa16(smem + BL_OFF + s * B_STG + e * 80 + seg * 16,
                  g_Wm + (size_t)e * D_DIM + k0 + seg * 8);
        }
        CP_COMMIT();
    };

    issue(0);
    issue(1);

    float c[2][4][4];
#pragma unroll
    for (int mt = 0; mt < 2; mt++)
#pragma unroll
        for (int nt = 0; nt < 4; nt++)
#pragma unroll
            for (int j = 0; j < 4; j++) c[mt][nt][j] = 0.f;

    for (int ci = 0; ci < NCH; ci++) {
        const int s = ci % 3;
        if (ci == NCH - 1) { CP_WAIT(0); } else { CP_WAIT(1); }
        __syncthreads();

        if (ci + 2 < NCH) issue(ci + 2);

        const char* As = smem + A_OFF + s * A_STG;
        const char* Bh = smem + BH_OFF + s * B_STG;
        const char* Bl = smem + BL_OFF + s * B_STG;

#pragma unroll
        for (int ks = 0; ks < 2; ks++) {              // k16 steps
            uint32_t ahi[2][4], alo[2][4];
#pragma unroll
            for (int mt = 0; mt < 2; mt++) {
                const char* ap = As + (wm * 32 + mt * 16 + g) * 160 + ks * 64 + tg * 8;
                float2 x0 = *(const float2*)ap;                 // row g,   k 2tg..+1
                float2 x2 = *(const float2*)(ap + 32);          // row g,   k +8
                float2 x1 = *(const float2*)(ap + 8 * 160);     // row g+8
                float2 x3 = *(const float2*)(ap + 8 * 160 + 32);
                splitpair(x0.x, x0.y, ahi[mt][0], alo[mt][0]);
                splitpair(x1.x, x1.y, ahi[mt][1], alo[mt][1]);
                splitpair(x2.x, x2.y, ahi[mt][2], alo[mt][2]);
                splitpair(x3.x, x3.y, ahi[mt][3], alo[mt][3]);
            }
#pragma unroll
            for (int nt = 0; nt < 4; nt++) {
                const char* pb = Bh + (wn * 32 + nt * 8 + g) * 80 + ks * 32 + tg * 4;
                uint32_t bh0 = *(const uint32_t*)pb;
                uint32_t bh1 = *(const uint32_t*)(pb + 16);
                const char* pl = Bl + (wn * 32 + nt * 8 + g) * 80 + ks * 32 + tg * 4;
                uint32_t bl0 = *(const uint32_t*)pl;
                uint32_t bl1 = *(const uint32_t*)(pl + 16);
#pragma unroll
                for (int mt = 0; mt < 2; mt++) {
                    mma_bf16(c[mt][nt], ahi[mt], bh0, bh1);   // hi*hi
                    mma_bf16(c[mt][nt], ahi[mt], bl0, bl1);   // hi*lo
                    mma_bf16(c[mt][nt], alo[mt], bh0, bh1);   // lo*hi
                }
            }
        }
    }
    __syncthreads();   // all MMAs done; A region free for logits staging

    // ---- scatter C frags to logits[128][LG_PAD] in smem
    float* lg = (float*)smem;
#pragma unroll
    for (int mt = 0; mt < 2; mt++)
#pragma unroll
        for (int nt = 0; nt < 4; nt++) {
            int rr = wm * 32 + mt * 16 + g, cc = wn * 32 + nt * 8 + tg * 2;
            *(float2*)&lg[rr * LG_PAD + cc]       = make_float2(c[mt][nt][0], c[mt][nt][1]);
            *(float2*)&lg[(rr + 8) * LG_PAD + cc] = make_float2(c[mt][nt][2], c[mt][nt][3]);
        }
    __syncthreads();

    if (tid < TILE_M) {
        const float* bs = (const float*)(smem + BIAS_OFF);
        const int myrow = row0 + tid;
        float v[64];
#pragma unroll
        for (int cc = 0; cc < NEXP; cc++) v[cc] = lg[tid * LG_PAD + cc] + bs[cc];

        float mx = -3.4e38f;
#pragma unroll
        for (int cc = 0; cc < NEXP; cc++) mx = fmaxf(mx, v[cc]);
        float ssum = 0.f;
#pragma unroll
        for (int cc = 0; cc < NEXP; cc++) ssum += __expf(v[cc] - mx);

        // top-9 sorted insert (8th + 9th for margin test)
        float t[9];
#pragma unroll
        for (int j = 0; j < 9; j++) t[j] = -3.4e38f;
#pragma unroll
        for (int cc = 0; cc < NEXP; cc++) {
            float x = v[cc];
#pragma unroll
            for (int j = 0; j < 9; j++) {
                float hi = fmaxf(t[j], x), lo = fminf(t[j], x);
                t[j] = hi; x = lo;
            }
        }
        float thr = t[7];
        unsigned long long msk = 0ull;

        if (thr - t[8] >= MARGIN) {
            int cnt_gt = 0;
#pragma unroll
            for (int cc = 0; cc < NEXP; cc++) cnt_gt += (v[cc] > thr) ? 1 : 0;
            int quota = 8 - cnt_gt, eq = 0;
#pragma unroll
            for (int cc = 0; cc < NEXP; cc++) {
                bool sg = v[cc] > thr;
                bool se = (v[cc] == thr) && (eq < quota);
                if (se) eq++;
                if (sg || se) msk |= 1ull << cc;
            }
        } else {
            // ambiguous boundary (~1% rows): exact fp32 recompute of candidates
            int   cidx[MAXC];
            float cval[MAXC];
            int nc = 0;
            float lim = thr - MARGIN;
            for (int cc = 0; cc < NEXP; cc++)
                if (v[cc] >= lim && nc < MAXC) { cidx[nc++] = cc; }

            const float* rrow = r + (size_t)myrow * D_DIM;
            for (int j = 0; j < nc; j++) {
                const float* wrow = W + (size_t)cidx[j] * D_DIM;
                float s0 = 0.f, s1 = 0.f, s2 = 0.f, s3 = 0.f;
                for (int k = 0; k < D_DIM; k += 4) {
                    float4 a = *(const float4*)(rrow + k);
                    float4 w = *(const float4*)(wrow + k);
                    s0 = fmaf(a.x, w.x, s0); s1 = fmaf(a.y, w.y, s1);
                    s2 = fmaf(a.z, w.z, s2); s3 = fmaf(a.w, w.w, s3);
                }
                cval[j] = (s0 + s1) + (s2 + s3) + bs[cidx[j]];
            }
            for (int it = 0; it < 8; it++) {
                float best = -3.4e38f; int bj = 0;
                for (int j = 0; j < nc; j++) {
                    bool freej = ((msk >> cidx[j]) & 1ull) == 0ull;
                    if (freej && cval[j] > best) { best = cval[j]; bj = j; }
                }
                msk |= 1ull << cidx[bj];
            }
        }

        float selexp = 0.f;
#pragma unroll
        for (int cc = 0; cc < NEXP; cc++)
            if ((msk >> cc) & 1ull) selexp += __expf(v[cc] - mx);

        float inv_s = 1.0f / ssum;
        float inv_d = 1.0f / (selexp * inv_s + 1e-9f);

        const size_t gr = (size_t)myrow * NEXP;
#pragma unroll
        for (int c4 = 0; c4 < NEXP; c4 += 4) {
            float sf[4], hd[4];
#pragma unroll
            for (int j = 0; j < 4; j++) {
                float soft = __expf(v[c4 + j] - mx) * inv_s;
                sf[j] = soft;
                hd[j] = ((msk >> (c4 + j)) & 1ull) ? soft * inv_d : 0.f;
            }
            *(float4*)(out + gr + c4)             = make_float4(hd[0], hd[1], hd[2], hd[3]);
            *(float4*)(out + soft_base + gr + c4) = make_float4(sf[0], sf[1], sf[2], sf[3]);
        }
    }
}

extern "C" void kernel_launch(void* const* d_in, const int* in_sizes, int n_in,
                              void* d_out, int out_size)
{
    const float* r = (const float*)d_in[0];   // (B, 2048) fp32
    const float* W = (const float*)d_in[1];   // (64, 2048) fp32
    const float* b = (const float*)d_in[2];   // (64,) fp32
    float* out = (float*)d_out;               // [hard | soft]

    int B = in_sizes[0] / D_DIM;              // 32768
    size_t soft_base = (size_t)out_size / 2;

    cudaFuncSetAttribute(moe_gate_mma, cudaFuncAttributeMaxDynamicSharedMemorySize, SMEM_TOTAL);

    conv_w_kernel<<<(NEXP * D_DIM) / 256, 256>>>(W);
    moe_gate_mma<<<B / TILE_M, NTHR, SMEM_TOTAL>>>(r, W, b, out, soft_base);
}